// round 5
// baseline (speedup 1.0000x reference)
#include <cuda_runtime.h>

// Problem constants (fixed by the reference)
#define TT     2048
#define CELLS  2048           // B*H
#define NSEG   64             // time segments
#define SEGLEN (TT / NSEG)    // 32 steps per segment
#define CHUNK  16             // pass-1 forcing prefetch chunk
#define NPAIRC (TT / (2 * CHUNK))  // 64 chunk-pairs in pass 1

// Scratch: boundary states at t = SEGLEN, 2*SEGLEN, ... (seg index 1..NSEG-1).
__device__ float2 g_bound[NSEG * CELLS];

// ---------------------------------------------------------------------------
// Pass 1: serial boundary scan. 1 thread per cell.
// Launched as 8 blocks x 256 threads -> 8 warps/SM -> 2 warps per SMSP so
// dependency-stall cycles of one warp are filled by its partner warp.
// 9-op body (6 fma-pipe, 3 alu-pipe).
// ---------------------------------------------------------------------------
__global__ __launch_bounds__(256, 1)
void pass1_kernel(const float2* __restrict__ F2,   // forcings [T, CELLS]
                  const float2* __restrict__ S02,  // initial states [CELLS]
                  const float4* __restrict__ P4)   // params [CELLS]
{
    const int cell = blockIdx.x * 256 + threadIdx.x;

    const float4 u = P4[cell];
    const float smax = 10.0f  + 490.0f  * u.x;
    const float k1   = 0.01f  + 0.89f   * u.y;
    const float k2   = 0.001f + 0.199f  * u.z;
    const float kb   = 0.001f + 0.099f  * u.w;

    const float inv  = 1.0f / smax;
    const float c1   = 1.0f - k1 - k2;
    const float c2   = 1.0f - kb;

    float2 s = S02[cell];
    float S1 = s.x, S2 = s.y;

    const float2* __restrict__ F = F2 + cell;

#define P1_STEP(fv)                                              \
    do {                                                         \
        const float Pf   = (fv).x;                               \
        const float Ef   = (fv).y;                               \
        const float frac = fminf(S1 * inv, 1.0f);                \
        const float et   = Ef * frac;                            \
        const float y    = fmaf(S1, c1, Pf);                     \
        const float prc  = k2 * S1;                              \
        S1 = fmaxf(y - et, 0.0f);                                \
        S2 = fmaxf(fmaf(S2, c2, prc), 0.0f);                     \
    } while (0)

    float2 bufA[CHUNK], bufB[CHUNK];

    // preload chunk 0
#pragma unroll
    for (int i = 0; i < CHUNK; i++)
        bufA[i] = F[i * CELLS];

#pragma unroll 1
    for (int cp = 0; cp < NPAIRC; cp++) {
        // prefetch chunk 2cp+1 -> bufB
        {
            const float2* Fn = F + (2 * cp + 1) * CHUNK * CELLS;
#pragma unroll
            for (int i = 0; i < CHUNK; i++)
                bufB[i] = Fn[i * CELLS];
        }
        // process chunk 2cp from bufA
#pragma unroll
        for (int i = 0; i < CHUNK; i++)
            P1_STEP(bufA[i]);

        // prefetch chunk 2cp+2 -> bufA
        if (cp + 1 < NPAIRC) {
            const float2* Fn = F + (2 * cp + 2) * CHUNK * CELLS;
#pragma unroll
            for (int i = 0; i < CHUNK; i++)
                bufA[i] = Fn[i * CELLS];
        }
        // process chunk 2cp+1 from bufB
#pragma unroll
        for (int i = 0; i < CHUNK; i++)
            P1_STEP(bufB[i]);

        // after pair cp: 32*(cp+1) steps done -> boundary at seg = cp+1
        if (cp != NPAIRC - 1) {
            g_bound[(cp + 1) * CELLS + cell] = make_float2(S1, S2);
        }
    }
#undef P1_STEP
}

// ---------------------------------------------------------------------------
// Pass 2: parallel segment replay. One thread = (cell, segment).
// Replays SEGLEN steps from the boundary state, writing fluxes AND states
// with reference-faithful arithmetic. Memory-bound by design.
// ---------------------------------------------------------------------------
__global__ __launch_bounds__(256)
void pass2_kernel(const float2* __restrict__ F2,   // forcings [T, CELLS]
                  const float2* __restrict__ S02,  // initial states [CELLS]
                  const float4* __restrict__ P4,   // params [CELLS]
                  float4* __restrict__ FX4,        // fluxes [T, CELLS]
                  float2* __restrict__ ST2)        // states [T, CELLS]
{
    const int cell = blockIdx.x * 256 + threadIdx.x;
    const int seg  = blockIdx.y;
    const int t0   = seg * SEGLEN;

    const float4 u = P4[cell];
    const float smax = 10.0f  + 490.0f  * u.x;
    const float k1   = 0.01f  + 0.89f   * u.y;
    const float k2   = 0.001f + 0.199f  * u.z;
    const float kb   = 0.001f + 0.099f  * u.w;
    const float inv  = 1.0f / smax;

    float2 s = (seg == 0) ? S02[cell] : g_bound[seg * CELLS + cell];
    float S1 = s.x, S2 = s.y;

    const float2* __restrict__ F  = F2  + (size_t)t0 * CELLS + cell;
    float4*       __restrict__ FX = FX4 + (size_t)t0 * CELLS + cell;
    float2*       __restrict__ ST = ST2 + (size_t)t0 * CELLS + cell;

#pragma unroll 4
    for (int i = 0; i < SEGLEN; i++) {
        const float2 f = F[i * CELLS];
        const float P   = f.x;
        const float PET = f.y;

        const float frac = fminf(S1 * inv, 1.0f);   // S1 >= 0 always
        const float et   = PET * frac;
        const float q1   = k1 * S1;
        const float perc = k2 * S1;
        const float qb   = kb * S2;

        FX[i * CELLS] = make_float4(et, q1, perc, qb);

        S1 = fmaxf(S1 + P - et - q1 - perc, 0.0f);
        S2 = fmaxf(S2 + perc - qb, 0.0f);

        ST[i * CELLS] = make_float2(S1, S2);
    }
}

extern "C" void kernel_launch(void* const* d_in, const int* in_sizes, int n_in,
                              void* d_out, int out_size)
{
    const float* forcings = (const float*)d_in[0];   // [T,B,H,2]
    const float* states0  = (const float*)d_in[1];   // [B,H,2]
    const float* params   = (const float*)d_in[2];   // [B,H,4]

    float* out = (float*)d_out;
    float* fluxes_out = out;                                   // [T,B,H,4]
    float* states_out = out + (size_t)TT * CELLS * 4;          // [T,B,H,2]

    pass1_kernel<<<CELLS / 256, 256>>>(
        reinterpret_cast<const float2*>(forcings),
        reinterpret_cast<const float2*>(states0),
        reinterpret_cast<const float4*>(params));

    pass2_kernel<<<dim3(CELLS / 256, NSEG), 256>>>(
        reinterpret_cast<const float2*>(forcings),
        reinterpret_cast<const float2*>(states0),
        reinterpret_cast<const float4*>(params),
        reinterpret_cast<float4*>(fluxes_out),
        reinterpret_cast<float2*>(states_out));
}